// round 1
// baseline (speedup 1.0000x reference)
#include <cuda_runtime.h>
#include <cstdint>
#include <cstddef>

#define EPSV  1e-6f
#define LNEPS 1e-5f

#define NB    4
#define LEN   16384
#define HN    8
#define DIM   16
#define NHT   (NB*HN)
#define ROWF  128          // HN*DIM floats per token row
#define ROW4  32           // float4 per token row

#define CH1    64
#define R1ROWS (LEN/CH1)   // 256
#define CH3    256
#define R3ROWS (LEN/CH3)   // 64
#define CH4    64
#define R4ROWS (LEN/CH4)   // 256

// ---------------- scratch (device globals; no runtime allocation) ----------
__device__ float g_p1q[NB*CH1*ROWF];
__device__ float g_p1k[NB*CH1*ROWF];
__device__ float g_p2q[NB*CH1*ROWF];
__device__ float g_p2k[NB*CH1*ROWF];
__device__ float g_qsum [NB*ROWF];
__device__ float g_ksum [NB*ROWF];
__device__ float g_qnsum[NB*ROWF];
__device__ float g_knsum[NB*ROWF];
__device__ float g_p3kv[(size_t)NB*CH3*HN*DIM*DIM];   // 8 MB
__device__ float g_p3se[NB*CH3*HN];
__device__ float g_kv[NHT*DIM*DIM];

// ---------------- helpers ---------------------------------------------------
__device__ __forceinline__ float sigmoidf(float x){
    float t;
    asm("tanh.approx.f32 %0, %1;" : "=f"(t) : "f"(0.5f*x));
    return fmaf(0.5f, t, 0.5f);
}
__device__ __forceinline__ float4 sigmoid4(float4 a){
    a.x = sigmoidf(a.x); a.y = sigmoidf(a.y);
    a.z = sigmoidf(a.z); a.w = sigmoidf(a.w);
    return a;
}

// ---------------- pass 1: ksum, qsum ---------------------------------------
__global__ void __launch_bounds__(256) p1_kernel(const float4* __restrict__ Q4,
                                                 const float4* __restrict__ K4){
    int n = blockIdx.y, ch = blockIdx.x;
    int t = threadIdx.x;
    int c4 = t & 31;
    int r0 = t >> 5;
    size_t base = ((size_t)n*LEN + (size_t)ch*R1ROWS)*ROW4 + c4;
    float4 aq = make_float4(0.f,0.f,0.f,0.f);
    float4 ak = make_float4(0.f,0.f,0.f,0.f);
    #pragma unroll 4
    for (int i = r0; i < R1ROWS; i += 8){
        float4 q = sigmoid4(Q4[base + (size_t)i*ROW4]);
        float4 k = sigmoid4(K4[base + (size_t)i*ROW4]);
        aq.x += q.x; aq.y += q.y; aq.z += q.z; aq.w += q.w;
        ak.x += k.x; ak.y += k.y; ak.z += k.z; ak.w += k.w;
    }
    __shared__ float4 red[256];
    red[t] = aq;
    __syncthreads();
    if (t < 128){
        int cc = t >> 2, comp = t & 3;
        float s = 0.f;
        #pragma unroll
        for (int r = 0; r < 8; ++r) s += ((const float*)&red[r*32 + cc])[comp];
        g_p1q[(n*CH1 + ch)*ROWF + t] = s;
    }
    __syncthreads();
    red[t] = ak;
    __syncthreads();
    if (t < 128){
        int cc = t >> 2, comp = t & 3;
        float s = 0.f;
        #pragma unroll
        for (int r = 0; r < 8; ++r) s += ((const float*)&red[r*32 + cc])[comp];
        g_p1k[(n*CH1 + ch)*ROWF + t] = s;
    }
}

__global__ void __launch_bounds__(128) r1_kernel(){
    int n = blockIdx.x, c = threadIdx.x;
    float sq = 0.f, sk = 0.f;
    #pragma unroll 8
    for (int ch = 0; ch < CH1; ++ch){
        sq += g_p1q[(n*CH1+ch)*ROWF + c];
        sk += g_p1k[(n*CH1+ch)*ROWF + c];
    }
    g_qsum[n*ROWF + c] = sq;
    g_ksum[n*ROWF + c] = sk;
}

// ---------------- pass 2: qnsum = sum q*nr ; knsum = sum k*nc ---------------
__global__ void __launch_bounds__(256) p2_kernel(const float4* __restrict__ Q4,
                                                 const float4* __restrict__ K4){
    __shared__ float sKs[ROWF], sQs[ROWF];
    __shared__ float epsK[HN], epsQ[HN];
    __shared__ float4 red[256];
    int n = blockIdx.y, ch = blockIdx.x;
    int t = threadIdx.x;
    if (t < ROWF){
        sKs[t] = g_ksum[n*ROWF + t] + EPSV;
        sQs[t] = g_qsum[n*ROWF + t] + EPSV;
    }
    __syncthreads();
    if (t < HN){
        float a = 0.f, b = 0.f;
        #pragma unroll
        for (int d = 0; d < DIM; ++d){ a += sKs[t*DIM+d]; b += sQs[t*DIM+d]; }
        epsK[t] = EPSV*a; epsQ[t] = EPSV*b;
    }
    __syncthreads();
    int c4 = t & 31, r0 = t >> 5;
    int h = c4 >> 2;
    float4 ke = *(const float4*)&sKs[c4*4];
    float4 qe = *(const float4*)&sQs[c4*4];
    float eK = epsK[h], eQ = epsQ[h];
    size_t base = ((size_t)n*LEN + (size_t)ch*R1ROWS)*ROW4 + c4;
    float4 aq = make_float4(0.f,0.f,0.f,0.f);
    float4 ak = make_float4(0.f,0.f,0.f,0.f);
    #pragma unroll 2
    for (int i = r0; i < R1ROWS; i += 8){
        float4 q = sigmoid4(Q4[base + (size_t)i*ROW4]);
        float4 k = sigmoid4(K4[base + (size_t)i*ROW4]);
        float dq = q.x*ke.x + q.y*ke.y + q.z*ke.z + q.w*ke.w;
        float dk = k.x*qe.x + k.y*qe.y + k.z*qe.z + k.w*qe.w;
        dq += __shfl_xor_sync(0xffffffffu, dq, 1);
        dk += __shfl_xor_sync(0xffffffffu, dk, 1);
        dq += __shfl_xor_sync(0xffffffffu, dq, 2);
        dk += __shfl_xor_sync(0xffffffffu, dk, 2);
        float nr = __fdividef(1.f, dq + eK);
        float nc = __fdividef(1.f, dk + eQ);
        aq.x = fmaf(q.x, nr, aq.x); aq.y = fmaf(q.y, nr, aq.y);
        aq.z = fmaf(q.z, nr, aq.z); aq.w = fmaf(q.w, nr, aq.w);
        ak.x = fmaf(k.x, nc, ak.x); ak.y = fmaf(k.y, nc, ak.y);
        ak.z = fmaf(k.z, nc, ak.z); ak.w = fmaf(k.w, nc, ak.w);
    }
    red[t] = aq;
    __syncthreads();
    if (t < 128){
        int cc = t >> 2, comp = t & 3;
        float s = 0.f;
        #pragma unroll
        for (int r = 0; r < 8; ++r) s += ((const float*)&red[r*32 + cc])[comp];
        g_p2q[(n*CH1 + ch)*ROWF + t] = s;
    }
    __syncthreads();
    red[t] = ak;
    __syncthreads();
    if (t < 128){
        int cc = t >> 2, comp = t & 3;
        float s = 0.f;
        #pragma unroll
        for (int r = 0; r < 8; ++r) s += ((const float*)&red[r*32 + cc])[comp];
        g_p2k[(n*CH1 + ch)*ROWF + t] = s;
    }
}

__global__ void __launch_bounds__(128) r2_kernel(){
    int n = blockIdx.x, c = threadIdx.x;
    float sq = 0.f, sk = 0.f;
    #pragma unroll 8
    for (int ch = 0; ch < CH1; ++ch){
        sq += g_p2q[(n*CH1+ch)*ROWF + c];
        sk += g_p2k[(n*CH1+ch)*ROWF + c];
    }
    g_qnsum[n*ROWF + c] = sq;
    g_knsum[n*ROWF + c] = sk;
}

// ---------------- pass 3: kv += exp(z_s) * k_s (outer) v_s ; sumexp ---------
#define SM3_BYTES ((2*R3ROWS*ROWF + R3ROWS*HN)*sizeof(float))

__global__ void __launch_bounds__(256) p3_kernel(const float4* __restrict__ K4,
                                                 const float4* __restrict__ V4){
    extern __shared__ float sm[];
    float* sk = sm;                       // 64*128
    float* sv = sm + R3ROWS*ROWF;         // 64*128
    float* sw = sm + 2*R3ROWS*ROWF;       // 64*8
    __shared__ float qnE[ROWF];
    __shared__ float epsq[HN];
    int n = blockIdx.y, ch = blockIdx.x;
    int t = threadIdx.x;
    if (t < ROWF) qnE[t] = g_qnsum[n*ROWF + t] + EPSV;
    __syncthreads();
    if (t < HN){
        float a = 0.f;
        #pragma unroll
        for (int d = 0; d < DIM; ++d) a += qnE[t*DIM + d];
        epsq[t] = EPSV*a;
    }
    __syncthreads();
    int c4 = t & 31, r0 = t >> 5;
    int h = c4 >> 2, q4i = c4 & 3;
    float4 qn4 = *(const float4*)&qnE[c4*4];
    float eq = epsq[h];
    size_t base = ((size_t)n*LEN + (size_t)ch*R3ROWS)*ROW4 + c4;
    float4* sk4 = (float4*)sk;
    float4* sv4 = (float4*)sv;
    #pragma unroll
    for (int i = r0; i < R3ROWS; i += 8){
        float4 k = sigmoid4(K4[base + (size_t)i*ROW4]);
        float4 v = V4[base + (size_t)i*ROW4];
        sk4[i*ROW4 + c4] = k;
        sv4[i*ROW4 + c4] = v;
        float pd = k.x*qn4.x + k.y*qn4.y + k.z*qn4.z + k.w*qn4.w;
        pd += __shfl_xor_sync(0xffffffffu, pd, 1);
        pd += __shfl_xor_sync(0xffffffffu, pd, 2);
        if (q4i == 0) sw[i*HN + h] = __expf(pd + eq);
    }
    __syncthreads();
    int hh  = t >> 5;
    int idx = t & 31;
    int d   = idx & 15;
    int eh  = idx >> 4;          // e-half: 0 -> e 0..7, 1 -> e 8..15
    float a0=0.f,a1=0.f,a2=0.f,a3=0.f,a4=0.f,a5=0.f,a6=0.f,a7=0.f;
    const float4* svr = (const float4*)sv;
    #pragma unroll 4
    for (int s = 0; s < R3ROWS; ++s){
        float w  = sw[s*HN + hh];
        float kk = sk[s*ROWF + hh*DIM + d];
        float wk = w*kk;
        float4 va = svr[s*ROW4 + hh*4 + eh*2];
        float4 vb = svr[s*ROW4 + hh*4 + eh*2 + 1];
        a0 = fmaf(wk, va.x, a0); a1 = fmaf(wk, va.y, a1);
        a2 = fmaf(wk, va.z, a2); a3 = fmaf(wk, va.w, a3);
        a4 = fmaf(wk, vb.x, a4); a5 = fmaf(wk, vb.y, a5);
        a6 = fmaf(wk, vb.z, a6); a7 = fmaf(wk, vb.w, a7);
    }
    size_t pb = (((size_t)(n*CH3 + ch))*HN + hh)*(DIM*DIM) + d*DIM + eh*8;
    *(float4*)&g_p3kv[pb]   = make_float4(a0,a1,a2,a3);
    *(float4*)&g_p3kv[pb+4] = make_float4(a4,a5,a6,a7);
    if (t < HN){
        float se = 0.f;
        #pragma unroll 8
        for (int s = 0; s < R3ROWS; ++s) se += sw[s*HN + t];
        g_p3se[(n*CH3 + ch)*HN + t] = se;
    }
}

__global__ void __launch_bounds__(256) r3_kernel(){
    __shared__ float sred[256];
    int nh = blockIdx.x;
    int n = nh >> 3, h = nh & 7;
    int t = threadIdx.x;
    sred[t] = g_p3se[(n*CH3 + t)*HN + h];
    __syncthreads();
    #pragma unroll
    for (int o = 128; o > 0; o >>= 1){
        if (t < o) sred[t] += sred[t + o];
        __syncthreads();
    }
    float scale = (float)LEN / sred[0];   // softmax * S folded into kv
    float acc = 0.f;
    #pragma unroll 16
    for (int ch = 0; ch < CH3; ++ch)
        acc += g_p3kv[(((size_t)(n*CH3 + ch))*HN + h)*(DIM*DIM) + t];
    g_kv[nh*(DIM*DIM) + t] = acc*scale;
}

// ---------------- pass 4: x = q@kv * nr * nrr + v ; LayerNorm ; store -------
__global__ void __launch_bounds__(256) p4_kernel(const float4* __restrict__ Q4,
                                                 const float4* __restrict__ V4,
                                                 const float*  __restrict__ gma,
                                                 const float*  __restrict__ bta,
                                                 float4* __restrict__ O4){
    __shared__ float kvs[HN*DIM*DIM];   // 8 KB
    __shared__ float sKs[ROWF], sKn[ROWF];
    __shared__ float epsK[HN], epsN[HN];
    __shared__ float sg[DIM], sb[DIM];
    int n = blockIdx.y, ch = blockIdx.x;
    int t = threadIdx.x;
    #pragma unroll
    for (int i = t; i < HN*DIM*DIM; i += 256) kvs[i] = g_kv[n*HN*DIM*DIM + i];
    if (t < ROWF){
        sKs[t] = g_ksum [n*ROWF + t] + EPSV;
        sKn[t] = g_knsum[n*ROWF + t] + EPSV;
    }
    if (t < DIM){ sg[t] = gma[t]; sb[t] = bta[t]; }
    __syncthreads();
    if (t < HN){
        float a = 0.f, b = 0.f;
        #pragma unroll
        for (int d = 0; d < DIM; ++d){ a += sKs[t*DIM+d]; b += sKn[t*DIM+d]; }
        epsK[t] = EPSV*a; epsN[t] = EPSV*b;
    }
    __syncthreads();
    int h = t >> 5, lane = t & 31;
    const float4* kv4 = (const float4*)&kvs[h*DIM*DIM];
    float eK = epsK[h], eN = epsN[h];
    size_t rowbase = ((size_t)n*LEN + (size_t)ch*R4ROWS + lane)*ROW4 + h*4;
    for (int i = 0; i < R4ROWS/32; ++i){
        size_t rb = rowbase + (size_t)(i*32)*ROW4;
        float4 q0 = sigmoid4(Q4[rb+0]);
        float4 q1 = sigmoid4(Q4[rb+1]);
        float4 q2 = sigmoid4(Q4[rb+2]);
        float4 q3 = sigmoid4(Q4[rb+3]);
        float qa[16];
        *(float4*)&qa[0]  = q0; *(float4*)&qa[4]  = q1;
        *(float4*)&qa[8]  = q2; *(float4*)&qa[12] = q3;
        float dr = eK, dn = eN;
        #pragma unroll
        for (int dd = 0; dd < DIM; ++dd){
            dr = fmaf(qa[dd], sKs[h*DIM + dd], dr);
            dn = fmaf(qa[dd], sKn[h*DIM + dd], dn);
        }
        float nr  = __fdividef(1.f, dr);
        float nrr = sigmoidf(dn);           // L/S == 1
        float sc  = nr*nrr;
        float4 x0 = make_float4(0.f,0.f,0.f,0.f);
        float4 x1 = x0, x2 = x0, x3 = x0;
        #pragma unroll
        for (int dd = 0; dd < DIM; ++dd){
            float qd = qa[dd];
            float4 c0 = kv4[dd*4+0];
            float4 c1 = kv4[dd*4+1];
            float4 c2 = kv4[dd*4+2];
            float4 c3 = kv4[dd*4+3];
            x0.x = fmaf(qd, c0.x, x0.x); x0.y = fmaf(qd, c0.y, x0.y);
            x0.z = fmaf(qd, c0.z, x0.z); x0.w = fmaf(qd, c0.w, x0.w);
            x1.x = fmaf(qd, c1.x, x1.x); x1.y = fmaf(qd, c1.y, x1.y);
            x1.z = fmaf(qd, c1.z, x1.z); x1.w = fmaf(qd, c1.w, x1.w);
            x2.x = fmaf(qd, c2.x, x2.x); x2.y = fmaf(qd, c2.y, x2.y);
            x2.z = fmaf(qd, c2.z, x2.z); x2.w = fmaf(qd, c2.w, x2.w);
            x3.x = fmaf(qd, c3.x, x3.x); x3.y = fmaf(qd, c3.y, x3.y);
            x3.z = fmaf(qd, c3.z, x3.z); x3.w = fmaf(qd, c3.w, x3.w);
        }
        float4 v0 = V4[rb+0], v1 = V4[rb+1], v2 = V4[rb+2], v3 = V4[rb+3];
        x0.x = fmaf(x0.x, sc, v0.x); x0.y = fmaf(x0.y, sc, v0.y);
        x0.z = fmaf(x0.z, sc, v0.z); x0.w = fmaf(x0.w, sc, v0.w);
        x1.x = fmaf(x1.x, sc, v1.x); x1.y = fmaf(x1.y, sc, v1.y);
        x1.z = fmaf(x1.z, sc, v1.z); x1.w = fmaf(x1.w, sc, v1.w);
        x2.x = fmaf(x2.x, sc, v2.x); x2.y = fmaf(x2.y, sc, v2.y);
        x2.z = fmaf(x2.z, sc, v2.z); x2.w = fmaf(x2.w, sc, v2.w);
        x3.x = fmaf(x3.x, sc, v3.x); x3.y = fmaf(x3.y, sc, v3.y);
        x3.z = fmaf(x3.z, sc, v3.z); x3.w = fmaf(x3.w, sc, v3.w);
        float m = ((x0.x+x0.y)+(x0.z+x0.w)) + ((x1.x+x1.y)+(x1.z+x1.w))
                + ((x2.x+x2.y)+(x2.z+x2.w)) + ((x3.x+x3.y)+(x3.z+x3.w));
        m *= 0.0625f;
        x0.x -= m; x0.y -= m; x0.z -= m; x0.w -= m;
        x1.x -= m; x1.y -= m; x1.z -= m; x1.w -= m;
        x2.x -= m; x2.y -= m; x2.z -= m; x2.w -= m;
        x3.x -= m; x3.y -= m; x3.z -= m; x3.w -= m;
        float var = x0.x*x0.x;
        var = fmaf(x0.y,x0.y,var); var = fmaf(x0.z,x0.z,var); var = fmaf(x0.w,x0.w,var);
        var = fmaf(x1.x,x1.x,var); var = fmaf(x1.y,x1.y,var); var = fmaf(x1.z,x1.z,var); var = fmaf(x1.w,x1.w,var);
        var = fmaf(x2.x,x2.x,var); var = fmaf(x2.y,x2.y,var); var = fmaf(x2.z,x2.z,var); var = fmaf(x2.w,x2.w,var);
        var = fmaf(x3.x,x3.x,var); var = fmaf(x3.y,x3.y,var); var = fmaf(x3.z,x3.z,var); var = fmaf(x3.w,x3.w,var);
        float rs = rsqrtf(fmaf(var, 0.0625f, LNEPS));
        float4 o0, o1, o2, o3;
        o0.x = fmaf(x0.x*rs, sg[0],  sb[0]);  o0.y = fmaf(x0.y*rs, sg[1],  sb[1]);
        o0.z = fmaf(x0.z*rs, sg[2],  sb[2]);  o0.w = fmaf(x0.w*rs, sg[3],  sb[3]);
        o1.x = fmaf(x1.x*rs, sg[4],  sb[4]);  o1.y = fmaf(x1.y*rs, sg[5],  sb[5]);
        o1.z = fmaf(x1.z*rs, sg[6],  sb[6]);  o1.w = fmaf(x1.w*rs, sg[7],  sb[7]);
        o2.x = fmaf(x2.x*rs, sg[8],  sb[8]);  o2.y = fmaf(x2.y*rs, sg[9],  sb[9]);
        o2.z = fmaf(x2.z*rs, sg[10], sb[10]); o2.w = fmaf(x2.w*rs, sg[11], sb[11]);
        o3.x = fmaf(x3.x*rs, sg[12], sb[12]); o3.y = fmaf(x3.y*rs, sg[13], sb[13]);
        o3.z = fmaf(x3.z*rs, sg[14], sb[14]); o3.w = fmaf(x3.w*rs, sg[15], sb[15]);
        O4[rb+0] = o0; O4[rb+1] = o1; O4[rb+2] = o2; O4[rb+3] = o3;
    }
}

// ---------------- launcher ---------------------------------------------------
extern "C" void kernel_launch(void* const* d_in, const int* in_sizes, int n_in,
                              void* d_out, int out_size){
    (void)in_sizes; (void)n_in; (void)out_size;
    const float4* Q = (const float4*)d_in[0];
    const float4* K = (const float4*)d_in[1];
    const float4* V = (const float4*)d_in[2];
    const float*  G = (const float*) d_in[3];
    const float*  B = (const float*) d_in[4];
    float4* O = (float4*)d_out;

    cudaFuncSetAttribute(p3_kernel, cudaFuncAttributeMaxDynamicSharedMemorySize,
                         (int)SM3_BYTES);

    dim3 g12(CH1, NB);
    dim3 g3 (CH3, NB);
    dim3 g4 (CH4, NB);
    p1_kernel<<<g12, 256>>>(Q, K);
    r1_kernel<<<NB, 128>>>();
    p2_kernel<<<g12, 256>>>(Q, K);
    r2_kernel<<<NB, 128>>>();
    p3_kernel<<<g3, 256, SM3_BYTES>>>(K, V);
    r3_kernel<<<NHT, 256>>>();
    p4_kernel<<<g4, 256>>>(Q, V, G, B, O);
}

// round 2
// speedup vs baseline: 1.0738x; 1.0738x over previous
#include <cuda_runtime.h>
#include <cstdint>
#include <cstddef>

#define EPSV  1e-6f
#define LNEPS 1e-5f

#define NB    4
#define LEN   16384
#define HN    8
#define DIM   16
#define ROWF  128          // HN*DIM floats per token row
#define ROW4  32           // float4 per token row

#define CH1   64
#define R1    (LEN/CH1)    // 256 rows per p1 block
#define CH2   64
#define R2    (LEN/CH2)    // 256 rows per p2 block
#define CH3   64
#define R3    (LEN/CH3)    // 256 rows per p3 block
#define SUB   64           // subtile rows in p3
#define NSUB  (R3/SUB)     // 4
#define CH4   128
#define R4    (LEN/CH4)    // 128 rows per p4 block

// ---------------- scratch (device globals; no runtime allocation) ----------
__device__ float g_p1q[NB*CH1*ROWF];
__device__ float g_p1k[NB*CH1*ROWF];
__device__ float g_p2q[NB*CH2*ROWF];
__device__ float g_p3kv[NB*CH3*HN*DIM*DIM];
__device__ float g_p3kn[NB*CH3*ROWF];
__device__ float g_p3se[NB*CH3*HN];
__device__ float g_ksum [NB*ROWF];
__device__ float g_knsum[NB*ROWF];
__device__ float g_kv[NB*HN*DIM*DIM];
__device__ int   g_cnt[NB];

// ---------------- helpers ---------------------------------------------------
__device__ __forceinline__ float sigmoidf(float x){
    float t;
    asm("tanh.approx.f32 %0, %1;" : "=f"(t) : "f"(0.5f*x));
    return fmaf(0.5f, t, 0.5f);
}
__device__ __forceinline__ float4 sigmoid4(float4 a){
    a.x = sigmoidf(a.x); a.y = sigmoidf(a.y);
    a.z = sigmoidf(a.z); a.w = sigmoidf(a.w);
    return a;
}

// ---------------- pass 1: qsum, ksum partials --------------------------------
__global__ void __launch_bounds__(256) p1_kernel(const float4* __restrict__ Q4,
                                                 const float4* __restrict__ K4){
    int n = blockIdx.y, ch = blockIdx.x;
    int t = threadIdx.x;
    int c4 = t & 31;
    int r0 = t >> 5;
    size_t base = ((size_t)n*LEN + (size_t)ch*R1)*ROW4 + c4;
    float4 aq = make_float4(0.f,0.f,0.f,0.f);
    float4 ak = make_float4(0.f,0.f,0.f,0.f);
    #pragma unroll 4
    for (int ii = 0; ii < R1/8; ++ii){
        size_t off = base + (size_t)(r0 + ii*8)*ROW4;
        float4 q = sigmoid4(Q4[off]);
        float4 k = sigmoid4(K4[off]);
        aq.x += q.x; aq.y += q.y; aq.z += q.z; aq.w += q.w;
        ak.x += k.x; ak.y += k.y; ak.z += k.z; ak.w += k.w;
    }
    __shared__ float4 red[256];
    red[t] = aq;
    __syncthreads();
    if (t < 128){
        int cc = t >> 2, comp = t & 3;
        float s = 0.f;
        #pragma unroll
        for (int r = 0; r < 8; ++r) s += ((const float*)&red[r*32 + cc])[comp];
        g_p1q[(n*CH1 + ch)*ROWF + t] = s;
    }
    __syncthreads();
    red[t] = ak;
    __syncthreads();
    if (t < 128){
        int cc = t >> 2, comp = t & 3;
        float s = 0.f;
        #pragma unroll
        for (int r = 0; r < 8; ++r) s += ((const float*)&red[r*32 + cc])[comp];
        g_p1k[(n*CH1 + ch)*ROWF + t] = s;
    }
}

// ---------------- pass 2: qnsum partials (reads Q only) ----------------------
__global__ void __launch_bounds__(256) p2_kernel(const float4* __restrict__ Q4){
    __shared__ float sKs[ROWF];
    __shared__ float epsK[HN];
    __shared__ float4 red[256];
    int n = blockIdx.y, ch = blockIdx.x;
    int t = threadIdx.x;
    if (t < ROWF){
        float s = 0.f;
        #pragma unroll 8
        for (int c = 0; c < CH1; ++c) s += g_p1k[(n*CH1+c)*ROWF + t];
        sKs[t] = s + EPSV;
    }
    __syncthreads();
    if (t < HN){
        float a = 0.f;
        #pragma unroll
        for (int d = 0; d < DIM; ++d) a += sKs[t*DIM+d];
        epsK[t] = EPSV*a;
    }
    __syncthreads();
    int c4 = t & 31, r0 = t >> 5;
    int h = c4 >> 2;
    float4 ke = *(const float4*)&sKs[c4*4];
    float eK = epsK[h];
    size_t base = ((size_t)n*LEN + (size_t)ch*R2)*ROW4 + c4;
    float4 aq = make_float4(0.f,0.f,0.f,0.f);
    #pragma unroll 4
    for (int ii = 0; ii < R2/8; ++ii){
        float4 q = sigmoid4(Q4[base + (size_t)(r0 + ii*8)*ROW4]);
        float dq = q.x*ke.x + q.y*ke.y + q.z*ke.z + q.w*ke.w;
        dq += __shfl_xor_sync(0xffffffffu, dq, 1);
        dq += __shfl_xor_sync(0xffffffffu, dq, 2);
        float nr = __fdividef(1.f, dq + eK);
        aq.x = fmaf(q.x, nr, aq.x); aq.y = fmaf(q.y, nr, aq.y);
        aq.z = fmaf(q.z, nr, aq.z); aq.w = fmaf(q.w, nr, aq.w);
    }
    red[t] = aq;
    __syncthreads();
    if (t < 128){
        int cc = t >> 2, comp = t & 3;
        float s = 0.f;
        #pragma unroll
        for (int r = 0; r < 8; ++r) s += ((const float*)&red[r*32 + cc])[comp];
        g_p2q[(n*CH2 + ch)*ROWF + t] = s;
    }
}

// ---------------- pass 3: kv, knsum, sumexp; last block finalizes ------------
#define SM3_BYTES ((2*SUB*ROWF + SUB*HN)*sizeof(float))

__global__ void __launch_bounds__(256) p3_kernel(const float4* __restrict__ K4,
                                                 const float4* __restrict__ V4){
    extern __shared__ float sm[];
    float* sk = sm;                    // SUB*ROWF
    float* sv = sm + SUB*ROWF;         // SUB*ROWF
    float* sw = sm + 2*SUB*ROWF;       // SUB*HN
    __shared__ float sQs[ROWF], qnE[ROWF];
    __shared__ float epsQ[HN], epsN[HN], sScale[HN];
    __shared__ int isLast;
    int n = blockIdx.y, ch = blockIdx.x;
    int t = threadIdx.x;
    if (t < ROWF){
        float a = 0.f, b = 0.f;
        #pragma unroll 8
        for (int c = 0; c < CH1; ++c) a += g_p1q[(n*CH1+c)*ROWF + t];
        #pragma unroll 8
        for (int c = 0; c < CH2; ++c) b += g_p2q[(n*CH2+c)*ROWF + t];
        sQs[t] = a + EPSV;
        qnE[t] = b + EPSV;
    }
    __syncthreads();
    if (t < HN){
        float a = 0.f, b = 0.f;
        #pragma unroll
        for (int d = 0; d < DIM; ++d){ a += sQs[t*DIM+d]; b += qnE[t*DIM+d]; }
        epsQ[t] = EPSV*a; epsN[t] = EPSV*b;
    }
    __syncthreads();
    int c4 = t & 31, r0 = t >> 5;
    int h = c4 >> 2, q4i = c4 & 3;
    float4 qs4 = *(const float4*)&sQs[c4*4];
    float4 qn4 = *(const float4*)&qnE[c4*4];
    float eQ = epsQ[h], eN = epsN[h];
    int hh = t >> 5, idx = t & 31;
    int d = idx & 15, eh = idx >> 4;
    float a0=0.f,a1=0.f,a2=0.f,a3=0.f,a4=0.f,a5=0.f,a6=0.f,a7=0.f;
    float se = 0.f;
    float4 akn = make_float4(0.f,0.f,0.f,0.f);
    size_t base0 = ((size_t)n*LEN + (size_t)ch*R3)*ROW4 + c4;
    float4* sk4 = (float4*)sk;
    float4* sv4 = (float4*)sv;
    const float4* svr = (const float4*)sv;
    for (int sub = 0; sub < NSUB; ++sub){
        size_t base = base0 + (size_t)(sub*SUB)*ROW4;
        #pragma unroll
        for (int ii = 0; ii < SUB/8; ++ii){
            int i = r0 + ii*8;
            float4 k = sigmoid4(K4[base + (size_t)i*ROW4]);
            float4 v = V4[base + (size_t)i*ROW4];
            sk4[i*ROW4 + c4] = k;
            sv4[i*ROW4 + c4] = v;
            float dk = k.x*qs4.x + k.y*qs4.y + k.z*qs4.z + k.w*qs4.w;
            float dn = k.x*qn4.x + k.y*qn4.y + k.z*qn4.z + k.w*qn4.w;
            dk += __shfl_xor_sync(0xffffffffu, dk, 1);
            dn += __shfl_xor_sync(0xffffffffu, dn, 1);
            dk += __shfl_xor_sync(0xffffffffu, dk, 2);
            dn += __shfl_xor_sync(0xffffffffu, dn, 2);
            float nc = __fdividef(1.f, dk + eQ);
            if (q4i == 0) sw[i*HN + h] = __expf(dn + eN);
            akn.x = fmaf(k.x, nc, akn.x); akn.y = fmaf(k.y, nc, akn.y);
            akn.z = fmaf(k.z, nc, akn.z); akn.w = fmaf(k.w, nc, akn.w);
        }
        __syncthreads();
        #pragma unroll 4
        for (int s = 0; s < SUB; ++s){
            float w  = sw[s*HN + hh];
            float kk = sk[s*ROWF + hh*DIM + d];
            float wk = w*kk;
            float4 va = svr[s*ROW4 + hh*4 + eh*2];
            float4 vb = svr[s*ROW4 + hh*4 + eh*2 + 1];
            a0 = fmaf(wk, va.x, a0); a1 = fmaf(wk, va.y, a1);
            a2 = fmaf(wk, va.z, a2); a3 = fmaf(wk, va.w, a3);
            a4 = fmaf(wk, vb.x, a4); a5 = fmaf(wk, vb.y, a5);
            a6 = fmaf(wk, vb.z, a6); a7 = fmaf(wk, vb.w, a7);
            se += w;
        }
        __syncthreads();
    }
    // kv partial (per-thread owns (h,d,eh) -> 8 e-values)
    size_t pb = (((size_t)(n*CH3 + ch))*HN + hh)*(DIM*DIM) + d*DIM + eh*8;
    *(float4*)&g_p3kv[pb]   = make_float4(a0,a1,a2,a3);
    *(float4*)&g_p3kv[pb+4] = make_float4(a4,a5,a6,a7);
    if (idx == 0) g_p3se[(n*CH3 + ch)*HN + hh] = se;
    // knsum partial: block reduce over 8 row-groups (reuse sk as scratch)
    float4* red4 = (float4*)sk;
    red4[t] = akn;
    __syncthreads();
    if (t < 128){
        int cc = t >> 2, comp = t & 3;
        float s = 0.f;
        #pragma unroll
        for (int r = 0; r < 8; ++r) s += ((const float*)&red4[r*32 + cc])[comp];
        g_p3kn[(n*CH3 + ch)*ROWF + t] = s;
    }
    // ---- last-block-per-batch finalization (deterministic fixed-order) ----
    __threadfence();
    __syncthreads();
    if (t == 0) isLast = (atomicAdd(&g_cnt[n], 1) == CH3-1) ? 1 : 0;
    __syncthreads();
    if (!isLast) return;
    __threadfence();
    if (t < HN){
        float s = 0.f;
        #pragma unroll 8
        for (int c = 0; c < CH3; ++c) s += g_p3se[(n*CH3+c)*HN + t];
        sScale[t] = (float)LEN / s;    // softmax * S folded into kv
    }
    __syncthreads();
    #pragma unroll
    for (int j = t; j < HN*DIM*DIM; j += 256){
        float acc = 0.f;
        #pragma unroll 8
        for (int c = 0; c < CH3; ++c)
            acc += g_p3kv[((size_t)(n*CH3 + c))*(HN*DIM*DIM) + j];
        g_kv[n*HN*DIM*DIM + j] = acc * sScale[j >> 8];
    }
    if (t < ROWF){
        float a = 0.f, b = 0.f;
        #pragma unroll 8
        for (int c = 0; c < CH1; ++c) a += g_p1k[(n*CH1+c)*ROWF + t];
        #pragma unroll 8
        for (int c = 0; c < CH3; ++c) b += g_p3kn[(n*CH3+c)*ROWF + t];
        g_ksum [n*ROWF + t] = a;
        g_knsum[n*ROWF + t] = b;
    }
    if (t == 0) g_cnt[n] = 0;          // reset for next graph replay
}

// ---------------- pass 4: x = q@kv * nr * nrr + v ; LayerNorm ; store -------
__global__ void __launch_bounds__(256) p4_kernel(const float4* __restrict__ Q4,
                                                 const float4* __restrict__ V4,
                                                 const float*  __restrict__ gma,
                                                 const float*  __restrict__ bta,
                                                 float4* __restrict__ O4){
    __shared__ float kvs[HN*DIM*DIM];   // 8 KB
    __shared__ float sKs[ROWF], sKn[ROWF];
    __shared__ float epsK[HN], epsN[HN];
    __shared__ float sg[DIM], sb[DIM];
    int n = blockIdx.y, ch = blockIdx.x;
    int t = threadIdx.x;
    #pragma unroll
    for (int i = t; i < HN*DIM*DIM; i += 256) kvs[i] = g_kv[n*HN*DIM*DIM + i];
    if (t < ROWF){
        sKs[t] = g_ksum [n*ROWF + t] + EPSV;
        sKn[t] = g_knsum[n*ROWF + t] + EPSV;
    }
    if (t < DIM){ sg[t] = gma[t]; sb[t] = bta[t]; }
    __syncthreads();
    if (t < HN){
        float a = 0.f, b = 0.f;
        #pragma unroll
        for (int d = 0; d < DIM; ++d){ a += sKs[t*DIM+d]; b += sKn[t*DIM+d]; }
        epsK[t] = EPSV*a; epsN[t] = EPSV*b;
    }
    __syncthreads();
    int h = t >> 5, lane = t & 31;
    const float4* kv4 = (const float4*)&kvs[h*DIM*DIM];
    float eK = epsK[h], eN = epsN[h];
    size_t rowbase = ((size_t)n*LEN + (size_t)ch*R4 + lane)*ROW4 + h*4;
    #pragma unroll
    for (int i = 0; i < R4/32; ++i){
        size_t rb = rowbase + (size_t)(i*32)*ROW4;
        float4 q0 = sigmoid4(Q4[rb+0]);
        float4 q1 = sigmoid4(Q4[rb+1]);
        float4 q2 = sigmoid4(Q4[rb+2]);
        float4 q3 = sigmoid4(Q4[rb+3]);
        float qa[16];
        *(float4*)&qa[0]  = q0; *(float4*)&qa[4]  = q1;
        *(float4*)&qa[8]  = q2; *(float4*)&qa[12] = q3;
        float dr = eK, dn = eN;
        #pragma unroll
        for (int dd = 0; dd < DIM; ++dd){
            dr = fmaf(qa[dd], sKs[h*DIM + dd], dr);
            dn = fmaf(qa[dd], sKn[h*DIM + dd], dn);
        }
        float nr  = __fdividef(1.f, dr);
        float nrr = sigmoidf(dn);           // L/S == 1
        float sc  = nr*nrr;
        float4 x0 = make_float4(0.f,0.f,0.f,0.f);
        float4 x1 = x0, x2 = x0, x3 = x0;
        #pragma unroll
        for (int dd = 0; dd < DIM; ++dd){
            float qd = qa[dd];
            float4 c0 = kv4[dd*4+0];
            float4 c1 = kv4[dd*4+1];
            float4 c2 = kv4[dd*4+2];
            float4 c3 = kv4[dd*4+3];
            x0.x = fmaf(qd, c0.x, x0.x); x0.y = fmaf(qd, c0.y, x0.y);
            x0.z = fmaf(qd, c0.z, x0.z); x0.w = fmaf(qd, c0.w, x0.w);
            x1.x = fmaf(qd, c1.x, x1.x); x1.y = fmaf(qd, c1.y, x1.y);
            x1.z = fmaf(qd, c1.z, x1.z); x1.w = fmaf(qd, c1.w, x1.w);
            x2.x = fmaf(qd, c2.x, x2.x); x2.y = fmaf(qd, c2.y, x2.y);
            x2.z = fmaf(qd, c2.z, x2.z); x2.w = fmaf(qd, c2.w, x2.w);
            x3.x = fmaf(qd, c3.x, x3.x); x3.y = fmaf(qd, c3.y, x3.y);
            x3.z = fmaf(qd, c3.z, x3.z); x3.w = fmaf(qd, c3.w, x3.w);
        }
        float4 v0 = V4[rb+0], v1 = V4[rb+1], v2 = V4[rb+2], v3 = V4[rb+3];
        x0.x = fmaf(x0.x, sc, v0.x); x0.y = fmaf(x0.y, sc, v0.y);
        x0.z = fmaf(x0.z, sc, v0.z); x0.w = fmaf(x0.w, sc, v0.w);
        x1.x = fmaf(x1.x, sc, v1.x); x1.y = fmaf(x1.y, sc, v1.y);
        x1.z = fmaf(x1.z, sc, v1.z); x1.w = fmaf(x1.w, sc, v1.w);
        x2.x = fmaf(x2.x, sc, v2.x); x2.y = fmaf(x2.y, sc, v2.y);
        x2.z = fmaf(x2.z, sc, v2.z); x2.w = fmaf(x2.w, sc, v2.w);
        x3.x = fmaf(x3.x, sc, v3.x); x3.y = fmaf(x3.y, sc, v3.y);
        x3.z = fmaf(x3.z, sc, v3.z); x3.w = fmaf(x3.w, sc, v3.w);
        float m = ((x0.x+x0.y)+(x0.z+x0.w)) + ((x1.x+x1.y)+(x1.z+x1.w))
                + ((x2.x+x2.y)+(x2.z+x2.w)) + ((x3.x+x3.y)+(x3.z+x3.w));
        m *= 0.0625f;
        x0.x -= m; x0.y -= m; x0.z -= m; x0.w -= m;
        x1.x -= m; x1.y -= m; x1.z -= m; x1.w -= m;
        x2.x -= m; x2.y -= m; x2.z -= m; x2.w -= m;
        x3.x -= m; x3.y -= m; x3.z -= m; x3.w -= m;
        float var = x0.x*x0.x;
        var = fmaf(x0.y,x0.y,var); var = fmaf(x0.z,x0.z,var); var = fmaf(x0.w,x0.w,var);
        var = fmaf(x1.x,x1.x,var); var = fmaf(x1.y,x1.y,var); var = fmaf(x1.z,x1.z,var); var = fmaf(x1.w,x1.w,var);
        var = fmaf(x2.x,x2.x,var); var = fmaf(x2.y,x2.y,var); var = fmaf(x2.z,x2.z,var); var = fmaf(x2.w,x2.w,var);
        var = fmaf(x3.x,x3.x,var); var = fmaf(x3.y,x3.y,var); var = fmaf(x3.z,x3.z,var); var = fmaf(x3.w,x3.w,var);
        float rs = rsqrtf(fmaf(var, 0.0625f, LNEPS));
        float4 o0, o1, o2, o3;
        o0.x = fmaf(x0.x*rs, sg[0],  sb[0]);  o0.y = fmaf(x0.y*rs, sg[1],  sb[1]);
        o0.z = fmaf(x0.z*rs, sg[2],  sb[2]);  o0.w = fmaf(x0.w*rs, sg[3],  sb[3]);
        o1.x = fmaf(x1.x*rs, sg[4],  sb[4]);  o1.y = fmaf(x1.y*rs, sg[5],  sb[5]);
        o1.z = fmaf(x1.z*rs, sg[6],  sb[6]);  o1.w = fmaf(x1.w*rs, sg[7],  sb[7]);
        o2.x = fmaf(x2.x*rs, sg[8],  sb[8]);  o2.y = fmaf(x2.y*rs, sg[9],  sb[9]);
        o2.z = fmaf(x2.z*rs, sg[10], sb[10]); o2.w = fmaf(x2.w*rs, sg[11], sb[11]);
        o3.x = fmaf(x3.x*rs, sg[12], sb[12]); o3.y = fmaf(x3.y*rs, sg[13], sb[13]);
        o3.z = fmaf(x3.z*rs, sg[14], sb[14]); o3.w = fmaf(x3.w*rs, sg[15], sb[15]);
        O4[rb+0] = o0; O4[rb+1] = o1; O4[rb+2] = o2; O4[rb+3] = o3;
    }
}

// ---------------- launcher ----------------------------------------------------
extern "C" void kernel_launch(void* const* d_in, const int* in_sizes, int n_in,
                              void* d_out, int out_size){
    (void)in_sizes; (void)n_in; (void)out_size;
    const float4* Q = (const float4*)d_in[0];
    const float4* K = (const float4*)d_in[1];
    const float4* V = (const float4*)d_in[2];
    const float*  G = (const float*) d_in[3];
    const float*  B = (const float*) d_in[4];
    float4* O = (float4*)d_out;

    static bool attr_done = false;
    if (!attr_done){
        cudaFuncSetAttribute(p3_kernel, cudaFuncAttributeMaxDynamicSharedMemorySize,
                             (int)SM3_BYTES);
        attr_done = true;
    }

    dim3 g1(CH1, NB), g2(CH2, NB), g3(CH3, NB), g4(CH4, NB);
    p1_kernel<<<g1, 256>>>(Q, K);
    p2_kernel<<<g2, 256>>>(Q);
    p3_kernel<<<g3, 256, SM3_BYTES>>>(K, V);
    p4_kernel<<<g4, 256>>>(Q, V, G, B, O);
}

// round 3
// speedup vs baseline: 1.1724x; 1.0918x over previous
#include <cuda_runtime.h>
#include <cuda_fp16.h>
#include <cstdint>
#include <cstddef>

#define EPSV  1e-6f
#define LNEPS 1e-5f

#define NB    4
#define LEN   16384
#define HN    8
#define DIM   16
#define ROWF  128          // HN*DIM floats per token row
#define ROW4  32           // float4 per token row

#define CH1   128
#define R1    (LEN/CH1)    // 128 rows per p1 block
#define CH2   128
#define R2    (LEN/CH2)    // 128
#define CH3   64
#define R3    (LEN/CH3)    // 256 rows per p3 block
#define SUB   64
#define NSUB  (R3/SUB)     // 4
#define TROWS 64           // p4 tile rows
#define CH4   (LEN/TROWS)  // 256 blocks per batch
#define TSTR  33           // p4 smem row stride in float4 (132 floats)

// ---------------- scratch ----------------------------------------------------
__device__ float g_p1q[NB*CH1*ROWF];
__device__ float g_p1k[NB*CH1*ROWF];
__device__ float g_p2q[NB*CH2*ROWF];
__device__ float g_p3kv[NB*CH3*HN*DIM*DIM];
__device__ float g_p3kn[NB*CH3*ROWF];
__device__ float g_p3se[NB*CH3*HN];
__device__ float g_ksum [NB*ROWF];
__device__ float g_knsum[NB*ROWF];
__device__ float g_kv[NB*HN*DIM*DIM];
__device__ int   g_cnt[NB];

// ---------------- helpers -----------------------------------------------------
__device__ __forceinline__ float sigmoidf1(float x){
    float t;
    asm("tanh.approx.f32 %0, %1;" : "=f"(t) : "f"(0.5f*x));
    return fmaf(0.5f, t, 0.5f);
}
// 2-wide sigmoid via tanh.approx.f16x2 (1 MUFU op per 2 elements)
__device__ __forceinline__ float2 sigmoid2f(float a, float b){
    __half2 h = __floats2half2_rn(a, b);
    h = __hmul2(h, __half2half2(__float2half_rn(0.5f)));
    uint32_t u = *reinterpret_cast<uint32_t*>(&h);
    asm("tanh.approx.f16x2 %0, %0;" : "+r"(u));
    __half2 th = *reinterpret_cast<__half2*>(&u);
    float2 f = __half22float2(th);
    f.x = fmaf(0.5f, f.x, 0.5f);
    f.y = fmaf(0.5f, f.y, 0.5f);
    return f;
}
__device__ __forceinline__ float4 sigmoid4(float4 a){
    float2 lo = sigmoid2f(a.x, a.y);
    float2 hi = sigmoid2f(a.z, a.w);
    return make_float4(lo.x, lo.y, hi.x, hi.y);
}

// ---------------- pass 1: qsum, ksum partials ---------------------------------
__global__ void __launch_bounds__(256) p1_kernel(const float4* __restrict__ Q4,
                                                 const float4* __restrict__ K4){
    int n = blockIdx.y, ch = blockIdx.x;
    int t = threadIdx.x;
    int c4 = t & 31, r0 = t >> 5;
    size_t base = ((size_t)n*LEN + (size_t)ch*R1)*ROW4 + c4;
    float4 aq = make_float4(0.f,0.f,0.f,0.f);
    float4 ak = make_float4(0.f,0.f,0.f,0.f);
    #pragma unroll 4
    for (int ii = 0; ii < R1/8; ++ii){
        size_t off = base + (size_t)(r0 + ii*8)*ROW4;
        float4 q = sigmoid4(Q4[off]);
        float4 k = sigmoid4(K4[off]);
        aq.x += q.x; aq.y += q.y; aq.z += q.z; aq.w += q.w;
        ak.x += k.x; ak.y += k.y; ak.z += k.z; ak.w += k.w;
    }
    __shared__ float4 red[256];
    red[t] = aq;
    __syncthreads();
    if (t < 128){
        int cc = t >> 2, comp = t & 3;
        float s = 0.f;
        #pragma unroll
        for (int r = 0; r < 8; ++r) s += ((const float*)&red[r*32 + cc])[comp];
        g_p1q[(n*CH1 + ch)*ROWF + t] = s;
    }
    __syncthreads();
    red[t] = ak;
    __syncthreads();
    if (t < 128){
        int cc = t >> 2, comp = t & 3;
        float s = 0.f;
        #pragma unroll
        for (int r = 0; r < 8; ++r) s += ((const float*)&red[r*32 + cc])[comp];
        g_p1k[(n*CH1 + ch)*ROWF + t] = s;
    }
}

// ---------------- pass 2: qnsum partials --------------------------------------
__global__ void __launch_bounds__(256) p2_kernel(const float4* __restrict__ Q4){
    __shared__ float sKs[ROWF];
    __shared__ float epsK[HN];
    __shared__ float4 red[256];
    int n = blockIdx.y, ch = blockIdx.x;
    int t = threadIdx.x;
    if (t < ROWF){
        float s = 0.f;
        #pragma unroll 8
        for (int c = 0; c < CH1; ++c) s += g_p1k[(n*CH1+c)*ROWF + t];
        sKs[t] = s + EPSV;
    }
    __syncthreads();
    if (t < HN){
        float a = 0.f;
        #pragma unroll
        for (int d = 0; d < DIM; ++d) a += sKs[t*DIM+d];
        epsK[t] = EPSV*a;
    }
    __syncthreads();
    int c4 = t & 31, r0 = t >> 5;
    int h = c4 >> 2;
    float4 ke = *(const float4*)&sKs[c4*4];
    float eK = epsK[h];
    size_t base = ((size_t)n*LEN + (size_t)ch*R2)*ROW4 + c4;
    float4 aq = make_float4(0.f,0.f,0.f,0.f);
    #pragma unroll 4
    for (int ii = 0; ii < R2/8; ++ii){
        float4 q = sigmoid4(Q4[base + (size_t)(r0 + ii*8)*ROW4]);
        float dq = q.x*ke.x + q.y*ke.y + q.z*ke.z + q.w*ke.w;
        dq += __shfl_xor_sync(0xffffffffu, dq, 1);
        dq += __shfl_xor_sync(0xffffffffu, dq, 2);
        float nr = __fdividef(1.f, dq + eK);
        aq.x = fmaf(q.x, nr, aq.x); aq.y = fmaf(q.y, nr, aq.y);
        aq.z = fmaf(q.z, nr, aq.z); aq.w = fmaf(q.w, nr, aq.w);
    }
    red[t] = aq;
    __syncthreads();
    if (t < 128){
        int cc = t >> 2, comp = t & 3;
        float s = 0.f;
        #pragma unroll
        for (int r = 0; r < 8; ++r) s += ((const float*)&red[r*32 + cc])[comp];
        g_p2q[(n*CH2 + ch)*ROWF + t] = s;
    }
}

// ---------------- pass 3: kv, knsum, sumexp; last block finalizes --------------
#define SM3_BYTES ((2*SUB*ROWF)*sizeof(float))

__global__ void __launch_bounds__(256) p3_kernel(const float4* __restrict__ K4,
                                                 const float4* __restrict__ V4){
    extern __shared__ float sm[];
    float* sk = sm;                    // SUB*ROWF   (holds w*k)
    float* sv = sm + SUB*ROWF;         // SUB*ROWF
    __shared__ float sQs[ROWF], qnE[ROWF];
    __shared__ float epsQ[HN], epsN[HN], sScale[HN];
    __shared__ int isLast;
    int n = blockIdx.y, ch = blockIdx.x;
    int t = threadIdx.x;
    if (t < ROWF){
        float a = 0.f, b = 0.f;
        #pragma unroll 8
        for (int c = 0; c < CH1; ++c) a += g_p1q[(n*CH1+c)*ROWF + t];
        #pragma unroll 8
        for (int c = 0; c < CH2; ++c) b += g_p2q[(n*CH2+c)*ROWF + t];
        sQs[t] = a + EPSV;
        qnE[t] = b + EPSV;
    }
    __syncthreads();
    if (t < HN){
        float a = 0.f, b = 0.f;
        #pragma unroll
        for (int d = 0; d < DIM; ++d){ a += sQs[t*DIM+d]; b += qnE[t*DIM+d]; }
        epsQ[t] = EPSV*a; epsN[t] = EPSV*b;
    }
    __syncthreads();
    int c4 = t & 31, r0 = t >> 5;
    int h = c4 >> 2, q4i = c4 & 3;
    float4 qs4 = *(const float4*)&sQs[c4*4];
    float4 qn4 = *(const float4*)&qnE[c4*4];
    float eQ = epsQ[h], eN = epsN[h];
    int hh = t >> 5, idx = t & 31;
    int d = idx & 15, eh = idx >> 4;
    float a0=0.f,a1=0.f,a2=0.f,a3=0.f,a4=0.f,a5=0.f,a6=0.f,a7=0.f;
    float se = 0.f;
    float4 akn = make_float4(0.f,0.f,0.f,0.f);
    size_t base0 = ((size_t)n*LEN + (size_t)ch*R3)*ROW4 + c4;
    float4* sk4 = (float4*)sk;
    float4* sv4 = (float4*)sv;
    const float4* svr = (const float4*)sv;
    for (int sub = 0; sub < NSUB; ++sub){
        size_t base = base0 + (size_t)(sub*SUB)*ROW4;
        #pragma unroll
        for (int ii = 0; ii < SUB/8; ++ii){
            int i = r0 + ii*8;
            float4 k = sigmoid4(K4[base + (size_t)i*ROW4]);
            float4 v = V4[base + (size_t)i*ROW4];
            sv4[i*ROW4 + c4] = v;
            float dk = k.x*qs4.x + k.y*qs4.y + k.z*qs4.z + k.w*qs4.w;
            float dn = k.x*qn4.x + k.y*qn4.y + k.z*qn4.z + k.w*qn4.w;
            dk += __shfl_xor_sync(0xffffffffu, dk, 1);
            dn += __shfl_xor_sync(0xffffffffu, dn, 1);
            dk += __shfl_xor_sync(0xffffffffu, dk, 2);
            dn += __shfl_xor_sync(0xffffffffu, dn, 2);
            float nc = __fdividef(1.f, dk + eQ);
            float w  = __expf(dn + eN);
            akn.x = fmaf(k.x, nc, akn.x); akn.y = fmaf(k.y, nc, akn.y);
            akn.z = fmaf(k.z, nc, akn.z); akn.w = fmaf(k.w, nc, akn.w);
            if (q4i == 0) se += w;
            k.x *= w; k.y *= w; k.z *= w; k.w *= w;   // premultiply
            sk4[i*ROW4 + c4] = k;
        }
        __syncthreads();
        #pragma unroll 4
        for (int s = 0; s < SUB; ++s){
            float wk = sk[s*ROWF + hh*DIM + d];
            float4 va = svr[s*ROW4 + hh*4 + eh*2];
            float4 vb = svr[s*ROW4 + hh*4 + eh*2 + 1];
            a0 = fmaf(wk, va.x, a0); a1 = fmaf(wk, va.y, a1);
            a2 = fmaf(wk, va.z, a2); a3 = fmaf(wk, va.w, a3);
            a4 = fmaf(wk, vb.x, a4); a5 = fmaf(wk, vb.y, a5);
            a6 = fmaf(wk, vb.z, a6); a7 = fmaf(wk, vb.w, a7);
        }
        __syncthreads();
    }
    // kv partial
    size_t pb = (((size_t)(n*CH3 + ch))*HN + hh)*(DIM*DIM) + d*DIM + eh*8;
    *(float4*)&g_p3kv[pb]   = make_float4(a0,a1,a2,a3);
    *(float4*)&g_p3kv[pb+4] = make_float4(a4,a5,a6,a7);
    // sumexp block-reduce (sv region as scratch)
    sv[t] = (q4i == 0) ? se : 0.f;
    // knsum partial reduce (sk region as scratch)
    float4* red4 = (float4*)sk;
    red4[t] = akn;
    __syncthreads();
    if (t < HN){
        float s = 0.f;
        #pragma unroll
        for (int r = 0; r < 8; ++r) s += sv[r*32 + t*4];
        g_p3se[(n*CH3 + ch)*HN + t] = s;
    }
    if (t < 128){
        int cc = t >> 2, comp = t & 3;
        float s = 0.f;
        #pragma unroll
        for (int r = 0; r < 8; ++r) s += ((const float*)&red4[r*32 + cc])[comp];
        g_p3kn[(n*CH3 + ch)*ROWF + t] = s;
    }
    // ---- last-block finalization ----
    __threadfence();
    __syncthreads();
    if (t == 0) isLast = (atomicAdd(&g_cnt[n], 1) == CH3-1) ? 1 : 0;
    __syncthreads();
    if (!isLast) return;
    __threadfence();
    if (t < HN){
        float s = 0.f;
        #pragma unroll 8
        for (int c = 0; c < CH3; ++c) s += g_p3se[(n*CH3+c)*HN + t];
        sScale[t] = (float)LEN / s;
    }
    __syncthreads();
    #pragma unroll
    for (int j = t; j < HN*DIM*DIM; j += 256){
        float acc = 0.f;
        #pragma unroll 8
        for (int c = 0; c < CH3; ++c)
            acc += g_p3kv[((size_t)(n*CH3 + c))*(HN*DIM*DIM) + j];
        g_kv[n*HN*DIM*DIM + j] = acc * sScale[j >> 8];
    }
    if (t < ROWF){
        float a = 0.f, b = 0.f;
        #pragma unroll 8
        for (int c = 0; c < CH1; ++c) a += g_p1k[(n*CH1+c)*ROWF + t];
        #pragma unroll 8
        for (int c = 0; c < CH3; ++c) b += g_p3kn[(n*CH3+c)*ROWF + t];
        g_ksum [n*ROWF + t] = a;
        g_knsum[n*ROWF + t] = b;
    }
    if (t == 0) g_cnt[n] = 0;
}

// ---------------- pass 4 ------------------------------------------------------
#define SM4_BYTES (TROWS*TSTR*4*sizeof(float))

__device__ __forceinline__ void p4_task(const float* q, int r, int h,
        float* smt, const float4* kv4, const float* sKs, const float* sKn,
        float eK, float eN, const float* sg, const float* sb)
{
    float dr = eK, dn = eN;
    #pragma unroll
    for (int dd = 0; dd < DIM; ++dd){
        dr = fmaf(q[dd], sKs[h*DIM + dd], dr);
        dn = fmaf(q[dd], sKn[h*DIM + dd], dn);
    }
    float nr  = __fdividef(1.f, dr);
    float nrr = sigmoidf1(dn);
    float sc  = nr*nrr;
    float x[16];
    #pragma unroll
    for (int e = 0; e < 16; ++e) x[e] = 0.f;
    #pragma unroll
    for (int dd = 0; dd < DIM; ++dd){
        float qd = q[dd];
        #pragma unroll
        for (int j = 0; j < 4; ++j){
            float4 c = kv4[dd*4 + j];
            x[j*4+0] = fmaf(qd, c.x, x[j*4+0]);
            x[j*4+1] = fmaf(qd, c.y, x[j*4+1]);
            x[j*4+2] = fmaf(qd, c.z, x[j*4+2]);
            x[j*4+3] = fmaf(qd, c.w, x[j*4+3]);
        }
    }
    float4* vp = (float4*)&smt[(r*TSTR + h*4)*4];
    float m = 0.f;
    #pragma unroll
    for (int j = 0; j < 4; ++j){
        float4 v = vp[j];
        x[j*4+0] = fmaf(x[j*4+0], sc, v.x);
        x[j*4+1] = fmaf(x[j*4+1], sc, v.y);
        x[j*4+2] = fmaf(x[j*4+2], sc, v.z);
        x[j*4+3] = fmaf(x[j*4+3], sc, v.w);
        m += (x[j*4+0] + x[j*4+1]) + (x[j*4+2] + x[j*4+3]);
    }
    m *= 0.0625f;
    float var = 0.f;
    #pragma unroll
    for (int e = 0; e < 16; ++e){ x[e] -= m; var = fmaf(x[e], x[e], var); }
    float rs = rsqrtf(fmaf(var, 0.0625f, LNEPS));
    #pragma unroll
    for (int j = 0; j < 4; ++j){
        float4 o;
        o.x = fmaf(x[j*4+0]*rs, sg[j*4+0], sb[j*4+0]);
        o.y = fmaf(x[j*4+1]*rs, sg[j*4+1], sb[j*4+1]);
        o.z = fmaf(x[j*4+2]*rs, sg[j*4+2], sb[j*4+2]);
        o.w = fmaf(x[j*4+3]*rs, sg[j*4+3], sb[j*4+3]);
        vp[j] = o;
    }
}

__global__ void __launch_bounds__(256, 3) p4_kernel(const float4* __restrict__ Q4,
                                                    const float4* __restrict__ V4,
                                                    const float*  __restrict__ gma,
                                                    const float*  __restrict__ bta,
                                                    float4* __restrict__ O4){
    extern __shared__ float smt[];          // TROWS x TSTR float4
    __shared__ float kvs[HN*DIM*DIM];       // 8 KB
    __shared__ float sKs[ROWF], sKn[ROWF];
    __shared__ float epsK[HN], epsN[HN];
    __shared__ float sg[DIM], sb[DIM];
    int n = blockIdx.y, ch = blockIdx.x;
    int t = threadIdx.x;
    #pragma unroll
    for (int i = t; i < HN*DIM*DIM; i += 256) kvs[i] = g_kv[n*HN*DIM*DIM + i];
    if (t < ROWF){
        sKs[t] = g_ksum [n*ROWF + t] + EPSV;
        sKn[t] = g_knsum[n*ROWF + t] + EPSV;
    }
    if (t < DIM){ sg[t] = gma[t]; sb[t] = bta[t]; }
    __syncthreads();
    if (t < HN){
        float a = 0.f, b = 0.f;
        #pragma unroll
        for (int d = 0; d < DIM; ++d){ a += sKs[t*DIM+d]; b += sKn[t*DIM+d]; }
        epsK[t] = EPSV*a; epsN[t] = EPSV*b;
    }
    __syncthreads();
    size_t gbase = ((size_t)n*LEN + (size_t)ch*TROWS)*ROW4;
    const float4* Qt = Q4 + gbase;
    const float4* Vt = V4 + gbase;
    float4*       Ot = O4 + gbase;
    float4* smt4 = (float4*)smt;
    // load Q tile (sigmoided), coalesced
    #pragma unroll
    for (int j = 0; j < 8; ++j){
        int idx = t + j*256;
        int row = idx >> 5, c = idx & 31;
        smt4[row*TSTR + c] = sigmoid4(Qt[idx]);
    }
    __syncthreads();
    int h = t >> 5, lane = t & 31;
    float qA[16], qB[16];
    #pragma unroll
    for (int j = 0; j < 4; ++j){
        *(float4*)&qA[j*4] = smt4[lane*TSTR + h*4 + j];
        *(float4*)&qB[j*4] = smt4[(lane+32)*TSTR + h*4 + j];
    }
    __syncthreads();
    // load V tile into same buffer
    #pragma unroll
    for (int j = 0; j < 8; ++j){
        int idx = t + j*256;
        int row = idx >> 5, c = idx & 31;
        smt4[row*TSTR + c] = Vt[idx];
    }
    __syncthreads();
    const float4* kv4 = (const float4*)&kvs[h*DIM*DIM];
    float eK = epsK[h], eN = epsN[h];
    p4_task(qA, lane,      h, smt, kv4, sKs, sKn, eK, eN, sg, sb);
    p4_task(qB, lane + 32, h, smt, kv4, sKs, sKn, eK, eN, sg, sb);
    __syncthreads();
    // store out, coalesced
    #pragma unroll
    for (int j = 0; j < 8; ++j){
        int idx = t + j*256;
        int row = idx >> 5, c = idx & 31;
        Ot[idx] = smt4[row*TSTR + c];
    }
}

// ---------------- launcher ------------------------------------------------------
extern "C" void kernel_launch(void* const* d_in, const int* in_sizes, int n_in,
                              void* d_out, int out_size){
    (void)in_sizes; (void)n_in; (void)out_size;
    const float4* Q = (const float4*)d_in[0];
    const float4* K = (const float4*)d_in[1];
    const float4* V = (const float4*)d_in[2];
    const float*  G = (const float*) d_in[3];
    const float*  B = (const float*) d_in[4];
    float4* O = (float4*)d_out;

    static bool attr_done = false;
    if (!attr_done){
        cudaFuncSetAttribute(p3_kernel, cudaFuncAttributeMaxDynamicSharedMemorySize,
                             (int)SM3_BYTES);
        cudaFuncSetAttribute(p4_kernel, cudaFuncAttributeMaxDynamicSharedMemorySize,
                             (int)SM4_BYTES);
        attr_done = true;
    }

    dim3 g1(CH1, NB), g2(CH2, NB), g3(CH3, NB), g4(CH4, NB);
    p1_kernel<<<g1, 256>>>(Q, K);
    p2_kernel<<<g2, 256>>>(Q);
    p3_kernel<<<g3, 256, SM3_BYTES>>>(K, V);
    p4_kernel<<<g4, 256, SM4_BYTES>>>(Q, V, G, B, O);
}

// round 4
// speedup vs baseline: 1.4929x; 1.2733x over previous
#include <cuda_runtime.h>
#include <cstdint>
#include <cstddef>

#define EPSV  1e-6f
#define LNEPS 1e-5f

#define NB    4
#define LEN   16384
#define HN    8
#define DIM   16
#define ROWF  128          // HN*DIM floats per token row
#define ROW4  32           // float4 per token row

#define CH1   64
#define R1    (LEN/CH1)    // 256 rows per p1 block
#define CH2   64
#define R2    (LEN/CH2)    // 256
#define CH3   64
#define R3    (LEN/CH3)    // 256 rows per p3 block
#define SUB   64
#define NSUB  (R3/SUB)     // 4
#define CH4   256          // p4 blocks per batch (64 tokens each)

// ---------------- scratch ----------------------------------------------------
__device__ float g_p1q[NB*CH1*ROWF];
__device__ float g_p1k[NB*CH1*ROWF];
__device__ float g_p2q[NB*CH2*ROWF];
__device__ float g_p3kv[NB*CH3*HN*DIM*DIM];
__device__ float g_p3kn[NB*CH3*ROWF];
__device__ float g_p3se[NB*CH3*HN];
__device__ float g_ksum [NB*ROWF];
__device__ float g_knsum[NB*ROWF];
__device__ float g_kv[NB*HN*DIM*DIM];

// ---------------- helpers -----------------------------------------------------
__device__ __forceinline__ float sigmoidf1(float x){
    float t;
    asm("tanh.approx.f32 %0, %1;" : "=f"(t) : "f"(0.5f*x));
    return fmaf(0.5f, t, 0.5f);
}
__device__ __forceinline__ float4 sigmoid4(float4 a){
    a.x = sigmoidf1(a.x); a.y = sigmoidf1(a.y);
    a.z = sigmoidf1(a.z); a.w = sigmoidf1(a.w);
    return a;
}

// ---------------- pass 1: qsum, ksum partials ---------------------------------
__global__ void __launch_bounds__(256) p1_kernel(const float4* __restrict__ Q4,
                                                 const float4* __restrict__ K4){
    int n = blockIdx.y, ch = blockIdx.x;
    int t = threadIdx.x;
    int c4 = t & 31, r0 = t >> 5;
    size_t base = ((size_t)n*LEN + (size_t)ch*R1)*ROW4 + c4;
    float4 aq = make_float4(0.f,0.f,0.f,0.f);
    float4 ak = make_float4(0.f,0.f,0.f,0.f);
    #pragma unroll 4
    for (int ii = 0; ii < R1/8; ++ii){
        size_t off = base + (size_t)(r0 + ii*8)*ROW4;
        float4 q = sigmoid4(Q4[off]);
        float4 k = sigmoid4(K4[off]);
        aq.x += q.x; aq.y += q.y; aq.z += q.z; aq.w += q.w;
        ak.x += k.x; ak.y += k.y; ak.z += k.z; ak.w += k.w;
    }
    __shared__ float4 red[256];
    red[t] = aq;
    __syncthreads();
    if (t < 128){
        int cc = t >> 2, comp = t & 3;
        float s = 0.f;
        #pragma unroll
        for (int r = 0; r < 8; ++r) s += ((const float*)&red[r*32 + cc])[comp];
        g_p1q[(n*CH1 + ch)*ROWF + t] = s;
    }
    __syncthreads();
    red[t] = ak;
    __syncthreads();
    if (t < 128){
        int cc = t >> 2, comp = t & 3;
        float s = 0.f;
        #pragma unroll
        for (int r = 0; r < 8; ++r) s += ((const float*)&red[r*32 + cc])[comp];
        g_p1k[(n*CH1 + ch)*ROWF + t] = s;
    }
}

// ---------------- pass 2: qnsum partials --------------------------------------
__global__ void __launch_bounds__(256) p2_kernel(const float4* __restrict__ Q4){
    __shared__ float sKs[ROWF];
    __shared__ float epsK[HN];
    __shared__ float4 red[256];
    int n = blockIdx.y, ch = blockIdx.x;
    int t = threadIdx.x;
    if (t < ROWF){
        float s = 0.f;
        #pragma unroll 8
        for (int c = 0; c < CH1; ++c) s += g_p1k[(n*CH1+c)*ROWF + t];
        sKs[t] = s + EPSV;
    }
    __syncthreads();
    if (t < HN){
        float a = 0.f;
        #pragma unroll
        for (int d = 0; d < DIM; ++d) a += sKs[t*DIM+d];
        epsK[t] = EPSV*a;
    }
    __syncthreads();
    int c4 = t & 31, r0 = t >> 5;
    int h = c4 >> 2;
    float4 ke = *(const float4*)&sKs[c4*4];
    float eK = epsK[h];
    size_t base = ((size_t)n*LEN + (size_t)ch*R2)*ROW4 + c4;
    float4 aq = make_float4(0.f,0.f,0.f,0.f);
    #pragma unroll 4
    for (int ii = 0; ii < R2/8; ++ii){
        float4 q = sigmoid4(Q4[base + (size_t)(r0 + ii*8)*ROW4]);
        float dq = q.x*ke.x + q.y*ke.y + q.z*ke.z + q.w*ke.w;
        dq += __shfl_xor_sync(0xffffffffu, dq, 1);
        dq += __shfl_xor_sync(0xffffffffu, dq, 2);
        float nr = __fdividef(1.f, dq + eK);
        aq.x = fmaf(q.x, nr, aq.x); aq.y = fmaf(q.y, nr, aq.y);
        aq.z = fmaf(q.z, nr, aq.z); aq.w = fmaf(q.w, nr, aq.w);
    }
    red[t] = aq;
    __syncthreads();
    if (t < 128){
        int cc = t >> 2, comp = t & 3;
        float s = 0.f;
        #pragma unroll
        for (int r = 0; r < 8; ++r) s += ((const float*)&red[r*32 + cc])[comp];
        g_p2q[(n*CH2 + ch)*ROWF + t] = s;
    }
}

// ---------------- pass 3: kv, knsum, sumexp partials ---------------------------
#define SM3_BYTES ((2*SUB*ROWF)*sizeof(float))

__global__ void __launch_bounds__(256) p3_kernel(const float4* __restrict__ K4,
                                                 const float4* __restrict__ V4){
    extern __shared__ float sm[];
    float* sk = sm;                    // SUB*ROWF   (holds w*k)
    float* sv = sm + SUB*ROWF;         // SUB*ROWF
    __shared__ float sQs[ROWF], qnE[ROWF];
    __shared__ float epsQ[HN], epsN[HN];
    int n = blockIdx.y, ch = blockIdx.x;
    int t = threadIdx.x;
    if (t < ROWF){
        float a = 0.f, b = 0.f;
        #pragma unroll 8
        for (int c = 0; c < CH1; ++c) a += g_p1q[(n*CH1+c)*ROWF + t];
        #pragma unroll 8
        for (int c = 0; c < CH2; ++c) b += g_p2q[(n*CH2+c)*ROWF + t];
        sQs[t] = a + EPSV;
        qnE[t] = b + EPSV;
    }
    __syncthreads();
    if (t < HN){
        float a = 0.f, b = 0.f;
        #pragma unroll
        for (int d = 0; d < DIM; ++d){ a += sQs[t*DIM+d]; b += qnE[t*DIM+d]; }
        epsQ[t] = EPSV*a; epsN[t] = EPSV*b;
    }
    __syncthreads();
    int c4 = t & 31, r0 = t >> 5;
    int h = c4 >> 2, q4i = c4 & 3;
    float4 qs4 = *(const float4*)&sQs[c4*4];
    float4 qn4 = *(const float4*)&qnE[c4*4];
    float eQ = epsQ[h], eN = epsN[h];
    int hh = t >> 5, idx = t & 31;
    int d = idx & 15, eh = idx >> 4;
    float a0=0.f,a1=0.f,a2=0.f,a3=0.f,a4=0.f,a5=0.f,a6=0.f,a7=0.f;
    float se = 0.f;
    float4 akn = make_float4(0.f,0.f,0.f,0.f);
    size_t base0 = ((size_t)n*LEN + (size_t)ch*R3)*ROW4 + c4;
    float4* sk4 = (float4*)sk;
    float4* sv4 = (float4*)sv;
    const float4* svr = (const float4*)sv;
    for (int sub = 0; sub < NSUB; ++sub){
        size_t base = base0 + (size_t)(sub*SUB)*ROW4;
        #pragma unroll
        for (int ii = 0; ii < SUB/8; ++ii){
            int i = r0 + ii*8;
            float4 k = sigmoid4(K4[base + (size_t)i*ROW4]);
            float4 v = V4[base + (size_t)i*ROW4];
            sv4[i*ROW4 + c4] = v;
            float dk = k.x*qs4.x + k.y*qs4.y + k.z*qs4.z + k.w*qs4.w;
            float dn = k.x*qn4.x + k.y*qn4.y + k.z*qn4.z + k.w*qn4.w;
            dk += __shfl_xor_sync(0xffffffffu, dk, 1);
            dn += __shfl_xor_sync(0xffffffffu, dn, 1);
            dk += __shfl_xor_sync(0xffffffffu, dk, 2);
            dn += __shfl_xor_sync(0xffffffffu, dn, 2);
            float nc = __fdividef(1.f, dk + eQ);
            float w  = __expf(dn + eN);
            akn.x = fmaf(k.x, nc, akn.x); akn.y = fmaf(k.y, nc, akn.y);
            akn.z = fmaf(k.z, nc, akn.z); akn.w = fmaf(k.w, nc, akn.w);
            if (q4i == 0) se += w;
            k.x *= w; k.y *= w; k.z *= w; k.w *= w;   // premultiply
            sk4[i*ROW4 + c4] = k;
        }
        __syncthreads();
        #pragma unroll 4
        for (int s = 0; s < SUB; ++s){
            float wk = sk[s*ROWF + hh*DIM + d];
            float4 va = svr[s*ROW4 + hh*4 + eh*2];
            float4 vb = svr[s*ROW4 + hh*4 + eh*2 + 1];
            a0 = fmaf(wk, va.x, a0); a1 = fmaf(wk, va.y, a1);
            a2 = fmaf(wk, va.z, a2); a3 = fmaf(wk, va.w, a3);
            a4 = fmaf(wk, vb.x, a4); a5 = fmaf(wk, vb.y, a5);
            a6 = fmaf(wk, vb.z, a6); a7 = fmaf(wk, vb.w, a7);
        }
        __syncthreads();
    }
    // kv partial
    size_t pb = (((size_t)(n*CH3 + ch))*HN + hh)*(DIM*DIM) + d*DIM + eh*8;
    *(float4*)&g_p3kv[pb]   = make_float4(a0,a1,a2,a3);
    *(float4*)&g_p3kv[pb+4] = make_float4(a4,a5,a6,a7);
    // sumexp block-reduce (sv region as scratch)
    sv[t] = (q4i == 0) ? se : 0.f;
    // knsum partial reduce (sk region as scratch)
    float4* red4 = (float4*)sk;
    red4[t] = akn;
    __syncthreads();
    if (t < HN){
        float s = 0.f;
        #pragma unroll
        for (int r = 0; r < 8; ++r) s += sv[r*32 + t*4];
        g_p3se[(n*CH3 + ch)*HN + t] = s;
    }
    if (t < 128){
        int cc = t >> 2, comp = t & 3;
        float s = 0.f;
        #pragma unroll
        for (int r = 0; r < 8; ++r) s += ((const float*)&red4[r*32 + cc])[comp];
        g_p3kn[(n*CH3 + ch)*ROWF + t] = s;
    }
}

// ---------------- rf: parallel finalize (kv, sumexp, ksum, knsum) -------------
__global__ void __launch_bounds__(256) rf_kernel(){
    __shared__ float sScale[HN];
    int b = blockIdx.x;
    int n = b >> 3, seg = b & 7;
    int t = threadIdx.x;
    if (t < HN){
        float s = 0.f;
        #pragma unroll 8
        for (int c = 0; c < CH3; ++c) s += g_p3se[(n*CH3+c)*HN + t];
        sScale[t] = (float)LEN / s;
    }
    __syncthreads();
    int j = seg*256 + t;
    float acc = 0.f;
    #pragma unroll 8
    for (int c = 0; c < CH3; ++c)
        acc += g_p3kv[((size_t)(n*CH3 + c))*(HN*DIM*DIM) + j];
    g_kv[n*(HN*DIM*DIM) + j] = acc * sScale[j >> 8];
    if (seg == 0 && t < ROWF){
        float a = 0.f, kb = 0.f;
        #pragma unroll 8
        for (int c = 0; c < CH1; ++c) a += g_p1k[(n*CH1+c)*ROWF + t];
        #pragma unroll 8
        for (int c = 0; c < CH3; ++c) kb += g_p3kn[(n*CH3+c)*ROWF + t];
        g_ksum [n*ROWF + t] = a;
        g_knsum[n*ROWF + t] = kb;
    }
}

// ---------------- pass 4: direct, shuffle-rotate matvec, no staging -----------
__global__ void __launch_bounds__(256, 2) p4_kernel(const float4* __restrict__ Q4,
                                                    const float4* __restrict__ V4,
                                                    const float*  __restrict__ gma,
                                                    const float*  __restrict__ bta,
                                                    float4* __restrict__ O4){
    __shared__ float kvs[HN*DIM*DIM];   // 8 KB
    __shared__ float sKs[ROWF], sKn[ROWF];
    __shared__ float epsK[HN], epsN[HN];
    __shared__ float sg[DIM], sb[DIM];
    int n = blockIdx.y, ch = blockIdx.x;
    int t = threadIdx.x;
    #pragma unroll
    for (int i = t; i < HN*DIM*DIM; i += 256) kvs[i] = g_kv[n*HN*DIM*DIM + i];
    if (t < ROWF){
        sKs[t] = g_ksum [n*ROWF + t] + EPSV;
        sKn[t] = g_knsum[n*ROWF + t] + EPSV;
    }
    if (t < DIM){ sg[t] = gma[t]; sb[t] = bta[t]; }
    __syncthreads();
    if (t < HN){
        float a = 0.f, bb = 0.f;
        #pragma unroll
        for (int d = 0; d < DIM; ++d){ a += sKs[t*DIM+d]; bb += sKn[t*DIM+d]; }
        epsK[t] = EPSV*a; epsN[t] = EPSV*bb;
    }
    __syncthreads();
    int warp = t >> 5, lane = t & 31;
    int h = lane >> 2, c = lane & 3;
    // per-lane constants in registers
    float4 kvr[16];   // [round r][j] = kv[d=(c^r)*4+j][e-chunk c]
    #pragma unroll
    for (int r = 0; r < 4; ++r){
        int ds = (c ^ r) * 4;
        #pragma unroll
        for (int j = 0; j < 4; ++j)
            kvr[r*4+j] = *(const float4*)&kvs[h*256 + (ds+j)*DIM + c*4];
    }
    float4 Ksl = *(const float4*)&sKs[h*DIM + c*4];
    float4 Knl = *(const float4*)&sKn[h*DIM + c*4];
    float4 gl  = *(const float4*)&sg[c*4];
    float4 bl  = *(const float4*)&sb[c*4];
    float eK = epsK[h], eN = epsN[h];
    size_t base = ((size_t)n*LEN + (size_t)ch*64 + (size_t)warp*8)*ROW4 + lane;
    const float4* Qp = Q4 + base;
    const float4* Vp = V4 + base;
    float4*       Op = O4 + base;
    float4 qc = Qp[0];
    float4 vc = Vp[0];
    #pragma unroll
    for (int tt = 0; tt < 8; ++tt){
        float4 qn_, vn_;
        if (tt < 7){ qn_ = Qp[(tt+1)*ROW4]; vn_ = Vp[(tt+1)*ROW4]; }
        float4 q = sigmoid4(qc);
        float pr = q.x*Ksl.x + q.y*Ksl.y + q.z*Ksl.z + q.w*Ksl.w;
        float pn = q.x*Knl.x + q.y*Knl.y + q.z*Knl.z + q.w*Knl.w;
        pr += __shfl_xor_sync(0xffffffffu, pr, 1);
        pn += __shfl_xor_sync(0xffffffffu, pn, 1);
        pr += __shfl_xor_sync(0xffffffffu, pr, 2);
        pn += __shfl_xor_sync(0xffffffffu, pn, 2);
        float sc = __fdividef(1.f, pr + eK) * sigmoidf1(pn + eN);
        float4 x = make_float4(0.f,0.f,0.f,0.f);
        // round 0: own q
        x.x = fmaf(q.x, kvr[0].x, x.x); x.y = fmaf(q.x, kvr[0].y, x.y);
        x.z = fmaf(q.x, kvr[0].z, x.z); x.w = fmaf(q.x, kvr[0].w, x.w);
        x.x = fmaf(q.y, kvr[1].x, x.x); x.y = fmaf(q.y, kvr[1].y, x.y);
        x.z = fmaf(q.y, kvr[1].z, x.z); x.w = fmaf(q.y, kvr[1].w, x.w);
        x.x = fmaf(q.z, kvr[2].x, x.x); x.y = fmaf(q.z, kvr[2].y, x.y);
        x.z = fmaf(q.z, kvr[2].z, x.z); x.w = fmaf(q.z, kvr[2].w, x.w);
        x.x = fmaf(q.w, kvr[3].x, x.x); x.y = fmaf(q.w, kvr[3].y, x.y);
        x.z = fmaf(q.w, kvr[3].z, x.z); x.w = fmaf(q.w, kvr[3].w, x.w);
        #pragma unroll
        for (int r = 1; r < 4; ++r){
            float4 qs;
            qs.x = __shfl_xor_sync(0xffffffffu, q.x, r);
            qs.y = __shfl_xor_sync(0xffffffffu, q.y, r);
            qs.z = __shfl_xor_sync(0xffffffffu, q.z, r);
            qs.w = __shfl_xor_sync(0xffffffffu, q.w, r);
            x.x = fmaf(qs.x, kvr[r*4+0].x, x.x); x.y = fmaf(qs.x, kvr[r*4+0].y, x.y);
            x.z = fmaf(qs.x, kvr[r*4+0].z, x.z); x.w = fmaf(qs.x, kvr[r*4+0].w, x.w);
            x.x = fmaf(qs.y, kvr[r*4+1].x, x.x); x.y = fmaf(qs.y, kvr[r*4+1].y, x.y);
            x.z = fmaf(qs.y, kvr[r*4+1].z, x.z); x.w = fmaf(qs.y, kvr[r*4+1].w, x.w);
            x.x = fmaf(qs.z, kvr[r*4+2].x, x.x); x.y = fmaf(qs.z, kvr[r*4+2].y, x.y);
            x.z = fmaf(qs.z, kvr[r*4+2].z, x.z); x.w = fmaf(qs.z, kvr[r*4+2].w, x.w);
            x.x = fmaf(qs.w, kvr[r*4+3].x, x.x); x.y = fmaf(qs.w, kvr[r*4+3].y, x.y);
            x.z = fmaf(qs.w, kvr[r*4+3].z, x.z); x.w = fmaf(qs.w, kvr[r*4+3].w, x.w);
        }
        x.x = fmaf(x.x, sc, vc.x); x.y = fmaf(x.y, sc, vc.y);
        x.z = fmaf(x.z, sc, vc.z); x.w = fmaf(x.w, sc, vc.w);
        float m = (x.x + x.y) + (x.z + x.w);
        m += __shfl_xor_sync(0xffffffffu, m, 1);
        m += __shfl_xor_sync(0xffffffffu, m, 2);
        m *= 0.0625f;
        x.x -= m; x.y -= m; x.z -= m; x.w -= m;
        float var = x.x*x.x;
        var = fmaf(x.y, x.y, var);
        var = fmaf(x.z, x.z, var);
        var = fmaf(x.w, x.w, var);
        var += __shfl_xor_sync(0xffffffffu, var, 1);
        var += __shfl_xor_sync(0xffffffffu, var, 2);
        float rs = rsqrtf(fmaf(var, 0.0625f, LNEPS));
        float4 o;
        o.x = fmaf(x.x*rs, gl.x, bl.x);
        o.y = fmaf(x.y*rs, gl.y, bl.y);
        o.z = fmaf(x.z*rs, gl.z, bl.z);
        o.w = fmaf(x.w*rs, gl.w, bl.w);
        Op[tt*ROW4] = o;
        qc = qn_; vc = vn_;
    }
}

// ---------------- launcher ------------------------------------------------------
extern "C" void kernel_launch(void* const* d_in, const int* in_sizes, int n_in,
                              void* d_out, int out_size){
    (void)in_sizes; (void)n_in; (void)out_size;
    const float4* Q = (const float4*)d_in[0];
    const float4* K = (const float4*)d_in[1];
    const float4* V = (const float4*)d_in[2];
    const float*  G = (const float*) d_in[3];
    const float*  B = (const float*) d_in[4];
    float4* O = (float4*)d_out;

    static bool attr_done = false;
    if (!attr_done){
        cudaFuncSetAttribute(p3_kernel, cudaFuncAttributeMaxDynamicSharedMemorySize,
                             (int)SM3_BYTES);
        attr_done = true;
    }

    dim3 g1(CH1, NB), g2(CH2, NB), g3(CH3, NB), g4(CH4, NB);
    p1_kernel<<<g1, 256>>>(Q, K);
    p2_kernel<<<g2, 256>>>(Q);
    p3_kernel<<<g3, 256, SM3_BYTES>>>(K, V);
    rf_kernel<<<NB*8, 256>>>();
    p4_kernel<<<g4, 256>>>(Q, V, G, B, O);
}